// round 7
// baseline (speedup 1.0000x reference)
#include <cuda_runtime.h>
#include <cstdint>

// ---------------------------------------------------------------------------
// Problem constants
// ---------------------------------------------------------------------------
#define RANK   64
#define NTOK   8192
#define KDIM   4096   // A1*B1 (GEMM contraction dim)
#define NDIM   4096   // A2*B2 (GEMM output cols)

// GEMM tiling: BM=256, BN=256, BK=16, 512 threads (16 warps, 4x4, 64x64 warp tile)
#define BM 256
#define BN 256
#define BK 16
#define NTHREADS 512
#define STAGES 5
#define AS_STRIDE 20                         // 16 + 4 pad: bank=(20g+c)%32 conflict-free
#define AS_FLOATS (BM * AS_STRIDE)           // 5120
#define BS_FLOATS (BK * BN)                  // 4096 (fragment-ordered, contiguous)
#define STAGE_FLOATS (AS_FLOATS + BS_FLOATS) // 9216
#define SMEM_BYTES (STAGES * STAGE_FLOATS * 4)   // 184320

// Scratch (static __device__ globals are the sanctioned no-alloc scratch)
__device__ float g_X[(size_t)NTOK * KDIM];     // tf32-rounded x (128 MB)
__device__ float g_W[(size_t)KDIM * NDIM];     // W in B-fragment order (64 MB)

__device__ __forceinline__ uint32_t f32_to_tf32(float f) {
    uint32_t r;
    asm("cvt.rna.tf32.f32 %0, %1;" : "=r"(r) : "f"(f));
    return r;
}

__device__ __forceinline__ void cp_async16(float* smem_dst, const float* gmem_src) {
    uint32_t s = (uint32_t)__cvta_generic_to_shared(smem_dst);
    asm volatile("cp.async.cg.shared.global [%0], [%1], 16;\n" :: "r"(s), "l"(gmem_src));
}

__device__ __forceinline__ void mma_tf32(float* d, const uint32_t* a, uint32_t b0, uint32_t b1) {
    asm volatile(
        "mma.sync.aligned.m16n8k8.row.col.f32.tf32.tf32.f32 "
        "{%0,%1,%2,%3}, {%4,%5,%6,%7}, {%8,%9}, {%0,%1,%2,%3};\n"
        : "+f"(d[0]), "+f"(d[1]), "+f"(d[2]), "+f"(d[3])
        : "r"(a[0]), "r"(a[1]), "r"(a[2]), "r"(a[3]), "r"(b0), "r"(b1));
}

// ---------------------------------------------------------------------------
// Kernel 1: round x to tf32 (rna) into g_X. One float4 per thread.
// ---------------------------------------------------------------------------
__global__ void cvt_x_kernel(const float* __restrict__ x) {
    int i = blockIdx.x * blockDim.x + threadIdx.x;
    float4 v = ((const float4*)x)[i];
    uint4 o;
    o.x = f32_to_tf32(v.x);
    o.y = f32_to_tf32(v.y);
    o.z = f32_to_tf32(v.z);
    o.w = f32_to_tf32(v.w);
    ((uint4*)g_X)[i] = o;
}

// ---------------------------------------------------------------------------
// Kernel 2: build W[K][n] = sum_r a[r,i,j]*b[r,kk,l]  (K = i*64+kk, n = j*64+l),
// tf32-rounded, stored in B-FRAGMENT order for mma.m16n8k8:
//   g_W[nb][k16][nsG][lane][q], value = W[k16*16 + c + 4q][nb*256 + nsG*8 + g]
//   where lane = g*4 + c. One CTA per W row K. (Verified in R5.)
// ---------------------------------------------------------------------------
__global__ void __launch_bounds__(256) build_w_kernel(const float* __restrict__ a,
                                                      const float* __restrict__ b) {
    __shared__ float sA[64 * 64];   // a[r][j] for fixed i
    __shared__ float sB[64 * 64];   // b[r][l] for fixed kk
    int K  = blockIdx.x;            // 0..4095
    int i  = K >> 6, kk = K & 63;
    int tid = threadIdx.x;

    for (int idx = tid; idx < 4096; idx += 256) {
        int r = idx >> 6, col = idx & 63;
        sA[idx] = a[r * 4096 + i  * 64 + col];
        sB[idx] = b[r * 4096 + kk * 64 + col];
    }
    __syncthreads();

    int tj = tid >> 4, tl = tid & 15;
    float acc[4][4];
    #pragma unroll
    for (int jj = 0; jj < 4; jj++)
        #pragma unroll
        for (int ll = 0; ll < 4; ll++) acc[jj][ll] = 0.0f;

    const float4* sA4 = (const float4*)sA;
    const float4* sB4 = (const float4*)sB;
    #pragma unroll 8
    for (int r = 0; r < 64; r++) {
        float4 av = sA4[r * 16 + tj];
        float4 bv = sB4[r * 16 + tl];
        float aj[4] = {av.x, av.y, av.z, av.w};
        float bl[4] = {bv.x, bv.y, bv.z, bv.w};
        #pragma unroll
        for (int jj = 0; jj < 4; jj++)
            #pragma unroll
            for (int ll = 0; ll < 4; ll++)
                acc[jj][ll] = fmaf(aj[jj], bl[ll], acc[jj][ll]);
    }

    int k16 = K >> 4, c = K & 3, q = (K >> 2) & 3;
    #pragma unroll
    for (int jj = 0; jj < 4; jj++) {
        int j = tj * 4 + jj;
        #pragma unroll
        for (int ll = 0; ll < 4; ll++) {
            int l  = tl * 4 + ll;
            int n  = j * 64 + l;
            int nb = n >> 8, nsG = (n >> 3) & 31, g = n & 7;
            int lane = (g << 2) | c;
            size_t idx = ((((size_t)nb * 256 + k16) * 32 + nsG) * 32 + lane) * 4 + q;
            g_W[idx] = __uint_as_float(f32_to_tf32(acc[jj][ll]));
        }
    }
}

// ---------------------------------------------------------------------------
// Kernel 3: GEMM out[8192,4096] = g_X @ W + bias, tf32 mma, fp32 accum.
// BM=256, BN=256, BK=16; 16 warps (4x4), warp tile 64x64.
// 5-stage cp.async ring, ONE __syncthreads per iteration.
// ---------------------------------------------------------------------------
__device__ __forceinline__ void load_tile(float* stage, int t,
                                          const float* Xg, const float* Wg, int tid) {
    // A: 256 rows x 16 floats -> 1024 float4 units (row = p>>2, u = p&3)
    float* As = stage;
    const float* xa = Xg + t * BK;
    #pragma unroll
    for (int it = 0; it < 2; it++) {
        int p = tid + it * NTHREADS;
        int row = p >> 2, u = p & 3;
        cp_async16(As + row * AS_STRIDE + u * 4, xa + (size_t)row * KDIM + u * 4);
    }
    // B: contiguous 16 KB fragment-ordered chunk (one k16 group)
    float* Bs = stage + AS_FLOATS;
    const float* wb = Wg + (size_t)t * BS_FLOATS;
    #pragma unroll
    for (int it = 0; it < 2; it++) {
        int p = tid + it * NTHREADS;
        cp_async16(Bs + p * 4, wb + p * 4);
    }
}

__global__ void __launch_bounds__(NTHREADS, 1)
gemm_kernel(const float* __restrict__ bias, float* __restrict__ out) {
    extern __shared__ float smem[];

    int tid  = threadIdx.x;
    int nb   = blockIdx.x;   // 0..15
    int mb   = blockIdx.y;   // 0..31
    int wid  = tid >> 5, lane = tid & 31;
    int wm   = wid >> 2;     // 0..3
    int wn   = wid & 3;      // 0..3
    int g    = lane >> 2, c = lane & 3;

    const float* Xg = g_X + (size_t)mb * BM * KDIM;
    const float* Wg = g_W + (size_t)nb * ((size_t)256 * KDIM);

    float acc[4][8][4];
    #pragma unroll
    for (int mt = 0; mt < 4; mt++)
        #pragma unroll
        for (int ns = 0; ns < 8; ns++)
            #pragma unroll
            for (int r = 0; r < 4; r++) acc[mt][ns][r] = 0.0f;

    // Prologue: load tiles 0..3 (4 groups outstanding)
    #pragma unroll
    for (int s = 0; s < STAGES - 1; s++) {
        load_tile(smem + s * STAGE_FLOATS, s, Xg, Wg, tid);
        asm volatile("cp.async.commit_group;\n");
    }

    const int NIT = KDIM / BK;   // 256
    int s_cur = 0, s_pre = STAGES - 1;
    for (int ki = 0; ki < NIT; ki++) {
        asm volatile("cp.async.wait_group %0;\n" :: "n"(STAGES - 2));  // tile ki ready
        __syncthreads();   // all threads' data visible; slot s_pre fully consumed

        // Prefetch tile ki+4 into the slot freed last iteration
        if (ki + STAGES - 1 < NIT)
            load_tile(smem + s_pre * STAGE_FLOATS, ki + STAGES - 1, Xg, Wg, tid);
        asm volatile("cp.async.commit_group;\n");   // always commit (keeps group count)

        const float* A_ = smem + s_cur * STAGE_FLOATS;
        const float* B_ = A_ + AS_FLOATS;

        float4 bv[8];
        #pragma unroll
        for (int ns = 0; ns < 8; ns++)
            bv[ns] = *(const float4*)(B_ + ((wn * 8 + ns) * 32 + lane) * 4);

        #pragma unroll
        for (int h = 0; h < 2; h++) {            // two k8 steps in BK=16
            uint32_t afr[4][4];
            #pragma unroll
            for (int mt = 0; mt < 4; mt++) {
                const float* ap = A_ + (wm * 64 + mt * 16 + g) * AS_STRIDE + h * 8 + c;
                afr[mt][0] = __float_as_uint(ap[0]);
                afr[mt][1] = __float_as_uint(ap[8 * AS_STRIDE]);
                afr[mt][2] = __float_as_uint(ap[4]);
                afr[mt][3] = __float_as_uint(ap[8 * AS_STRIDE + 4]);
            }
            #pragma unroll
            for (int mt = 0; mt < 4; mt++) {
                #pragma unroll
                for (int ns = 0; ns < 8; ns++) {
                    uint32_t b0 = h ? __float_as_uint(bv[ns].z) : __float_as_uint(bv[ns].x);
                    uint32_t b1 = h ? __float_as_uint(bv[ns].w) : __float_as_uint(bv[ns].y);
                    mma_tf32(acc[mt][ns], afr[mt], b0, b1);
                }
            }
        }

        s_pre = s_cur;
        s_cur = (s_cur + 1 == STAGES) ? 0 : s_cur + 1;
    }

    // Epilogue: add bias, write fp32
    int nbase = nb * 256 + wn * 64;
    int mbase = mb * BM + wm * 64;
    float2 bcol[8];
    #pragma unroll
    for (int ns = 0; ns < 8; ns++) {
        int col = nbase + ns * 8 + 2 * c;
        bcol[ns] = make_float2(bias[col], bias[col + 1]);
    }
    #pragma unroll
    for (int mt = 0; mt < 4; mt++) {
        int r0 = mbase + mt * 16 + g;
        #pragma unroll
        for (int ns = 0; ns < 8; ns++) {
            int col = nbase + ns * 8 + 2 * c;
            float2 v0 = make_float2(acc[mt][ns][0] + bcol[ns].x, acc[mt][ns][1] + bcol[ns].y);
            float2 v1 = make_float2(acc[mt][ns][2] + bcol[ns].x, acc[mt][ns][3] + bcol[ns].y);
            *(float2*)(out + (size_t)r0 * NDIM + col)       = v0;
            *(float2*)(out + (size_t)(r0 + 8) * NDIM + col) = v1;
        }
    }
}

// ---------------------------------------------------------------------------
extern "C" void kernel_launch(void* const* d_in, const int* in_sizes, int n_in,
                              void* d_out, int out_size) {
    const float *x = nullptr, *a = nullptr, *b = nullptr, *bias = nullptr;
    for (int idx = 0; idx < n_in; ++idx) {
        int s = in_sizes[idx];
        if (s == NTOK * KDIM && !x) x = (const float*)d_in[idx];
        else if (s == RANK * 64 * 64) { if (!a) a = (const float*)d_in[idx]; else if (!b) b = (const float*)d_in[idx]; }
        else if (s == NDIM && !bias) bias = (const float*)d_in[idx];
    }
    if (!x)    x    = (const float*)d_in[0];
    if (!a)    a    = (const float*)d_in[1];
    if (!b)    b    = (const float*)d_in[2];
    if (!bias) bias = (const float*)d_in[3];
    float* out = (float*)d_out;

    cvt_x_kernel<<<(NTOK * KDIM) / 4 / 256, 256>>>(x);
    build_w_kernel<<<KDIM, 256>>>(a, b);

    cudaFuncSetAttribute(gemm_kernel, cudaFuncAttributeMaxDynamicSharedMemorySize, SMEM_BYTES);
    dim3 grid(NDIM / BN, NTOK / BM);   // (16, 32)
    gemm_kernel<<<grid, NTHREADS, SMEM_BYTES>>>(bias, out);
}

// round 8
// speedup vs baseline: 8.1964x; 8.1964x over previous
#include <cuda_runtime.h>
#include <cuda_bf16.h>
#include <cstdint>

// ---------------------------------------------------------------------------
// Problem constants
// ---------------------------------------------------------------------------
#define RANK   64
#define NTOK   8192
#define KDIM   4096   // A1*B1 (GEMM contraction dim)
#define NDIM   4096   // A2*B2 (GEMM output cols)

// GEMM tiling: BM=128, BN=256, BK=32, 256 threads (8 warps 2x4, 64x64 warp tile)
#define BM 128
#define BN 256
#define BK 32
#define NTHREADS 256
#define STAGES 4
// A stage: 128 rows x 16 u32 (k-pairs) padded to 20 -> conflict-free frag loads
#define AS_STRIDE 20
#define AS_U32 (BM * AS_STRIDE)              // 2560
#define BS_U32 (BN * BK / 2)                 // 4096 (fragment-ordered, contiguous)
#define STAGE_U32 (AS_U32 + BS_U32)          // 6656
#define SMEM_BYTES (STAGES * STAGE_U32 * 4)  // 106496

// Scratch (static __device__ globals are the sanctioned no-alloc scratch)
__device__ __nv_bfloat16 g_Xh[(size_t)NTOK * KDIM];  // bf16 x (64 MB)
__device__ uint32_t g_Wp[(size_t)KDIM * NDIM / 2];   // W bf16x2, B-fragment order (32 MB)

__device__ __forceinline__ void cp_async16(uint32_t* smem_dst, const void* gmem_src) {
    uint32_t s = (uint32_t)__cvta_generic_to_shared(smem_dst);
    asm volatile("cp.async.cg.shared.global [%0], [%1], 16;\n" :: "r"(s), "l"(gmem_src));
}

// m16n8k16 bf16 mma, fp32 accumulate
__device__ __forceinline__ void mma_bf16(float* d, const uint32_t* a, uint32_t b0, uint32_t b1) {
    asm volatile(
        "mma.sync.aligned.m16n8k16.row.col.f32.bf16.bf16.f32 "
        "{%0,%1,%2,%3}, {%4,%5,%6,%7}, {%8,%9}, {%0,%1,%2,%3};\n"
        : "+f"(d[0]), "+f"(d[1]), "+f"(d[2]), "+f"(d[3])
        : "r"(a[0]), "r"(a[1]), "r"(a[2]), "r"(a[3]), "r"(b0), "r"(b1));
}

__device__ __forceinline__ uint32_t pack_bf16x2(float lo, float hi) {
    __nv_bfloat162 h = __floats2bfloat162_rn(lo, hi);   // x = lo (low 16 bits)
    return *(uint32_t*)&h;
}

// ---------------------------------------------------------------------------
// Kernel 1: convert x fp32 -> bf16 (rn). 8 floats per thread.
// ---------------------------------------------------------------------------
__global__ void cvt_x_kernel(const float* __restrict__ x) {
    int i = blockIdx.x * blockDim.x + threadIdx.x;   // 8-float chunk index
    float4 v0 = ((const float4*)x)[i * 2];
    float4 v1 = ((const float4*)x)[i * 2 + 1];
    uint4 o;
    o.x = pack_bf16x2(v0.x, v0.y);
    o.y = pack_bf16x2(v0.z, v0.w);
    o.z = pack_bf16x2(v1.x, v1.y);
    o.w = pack_bf16x2(v1.z, v1.w);
    ((uint4*)g_Xh)[i] = o;
}

// ---------------------------------------------------------------------------
// Kernel 2: build W[K][n] = sum_r a[r,i,j]*b[r,kk,l] (K = i*64+kk, n = j*64+l)
// in bf16, packed as (K even, K odd) pairs in m16n8k16 B-fragment order:
//   g_Wp[nb][k32][nsG][lane][q] : lane = (n&7)*4 + c,
//   q = 2*half + (koff>=8), K = k32*32 + half*16 + koff, koff even, c=(koff&7)>>1,
//   u32 = {lo: W[K][n], hi: W[K+1][n]}.
// One CTA per even K (2048 CTAs); fp32 accumulation, 4x4x2 register tile.
// ---------------------------------------------------------------------------
__global__ void __launch_bounds__(256) build_w_kernel(const float* __restrict__ a,
                                                      const float* __restrict__ b) {
    __shared__ float sA [64 * 64];   // a[r][j] for fixed i
    __shared__ float sB0[64 * 64];   // b[r][kk][l]
    __shared__ float sB1[64 * 64];   // b[r][kk+1][l]
    int K0 = blockIdx.x * 2;         // even K
    int i  = K0 >> 6, kk = K0 & 63;
    int tid = threadIdx.x;

    for (int idx = tid; idx < 4096; idx += 256) {
        int r = idx >> 6, col = idx & 63;
        sA [idx] = a[r * 4096 + i * 64 + col];
        sB0[idx] = b[r * 4096 + kk * 64 + col];
        sB1[idx] = b[r * 4096 + (kk + 1) * 64 + col];
    }
    __syncthreads();

    int tj = tid >> 4, tl = tid & 15;
    float accE[4][4], accO[4][4];
    #pragma unroll
    for (int jj = 0; jj < 4; jj++)
        #pragma unroll
        for (int ll = 0; ll < 4; ll++) { accE[jj][ll] = 0.0f; accO[jj][ll] = 0.0f; }

    const float4* A4  = (const float4*)sA;
    const float4* B04 = (const float4*)sB0;
    const float4* B14 = (const float4*)sB1;
    #pragma unroll 4
    for (int r = 0; r < 64; r++) {
        float4 av  = A4 [r * 16 + tj];
        float4 bv0 = B04[r * 16 + tl];
        float4 bv1 = B14[r * 16 + tl];
        float aj[4]  = {av.x, av.y, av.z, av.w};
        float bE[4]  = {bv0.x, bv0.y, bv0.z, bv0.w};
        float bO[4]  = {bv1.x, bv1.y, bv1.z, bv1.w};
        #pragma unroll
        for (int jj = 0; jj < 4; jj++)
            #pragma unroll
            for (int ll = 0; ll < 4; ll++) {
                accE[jj][ll] = fmaf(aj[jj], bE[ll], accE[jj][ll]);
                accO[jj][ll] = fmaf(aj[jj], bO[ll], accO[jj][ll]);
            }
    }

    int k32  = K0 >> 5;
    int r5   = K0 & 31;
    int half = r5 >> 4;
    int koff = r5 & 15;                 // even
    int c    = (koff & 7) >> 1;
    int q    = 2 * half + (koff >= 8 ? 1 : 0);

    #pragma unroll
    for (int jj = 0; jj < 4; jj++) {
        int j = tj * 4 + jj;
        #pragma unroll
        for (int ll = 0; ll < 4; ll++) {
            int l  = tl * 4 + ll;
            int n  = j * 64 + l;
            int nb = n >> 8, nsG = (n >> 3) & 31, g = n & 7;
            int lane = (g << 2) | c;
            size_t idx = ((((size_t)nb * 128 + k32) * 32 + nsG) * 32 + lane) * 4 + q;
            g_Wp[idx] = pack_bf16x2(accE[jj][ll], accO[jj][ll]);
        }
    }
}

// ---------------------------------------------------------------------------
// Kernel 3: GEMM out[8192,4096] = x @ W + bias, bf16 mma, fp32 accum.
// BM=128, BN=256, BK=32; 4-stage cp.async ring, wait_group 2, one sync/iter.
// ---------------------------------------------------------------------------
__device__ __forceinline__ void load_tile(uint32_t* stage, int t,
                                          const __nv_bfloat16* Xg, const uint32_t* Wg,
                                          int tid) {
    // A: 128 rows x 32 bf16 (64B) -> 512 x 16B units (row = p>>2, u = p&3)
    uint32_t* As = stage;
    const __nv_bfloat16* xa = Xg + t * BK;
    #pragma unroll
    for (int it = 0; it < 2; it++) {
        int p = tid + it * NTHREADS;
        int row = p >> 2, u = p & 3;
        cp_async16(As + row * AS_STRIDE + u * 4, xa + (size_t)row * KDIM + u * 8);
    }
    // B: contiguous 16 KB fragment-ordered chunk (one k32 group)
    uint32_t* Bs = stage + AS_U32;
    const uint32_t* wb = Wg + (size_t)t * BS_U32;
    #pragma unroll
    for (int it = 0; it < 4; it++) {
        int p = tid + it * NTHREADS;
        cp_async16(Bs + p * 4, wb + p * 4);
    }
}

__global__ void __launch_bounds__(NTHREADS, 1)
gemm_kernel(const float* __restrict__ bias, float* __restrict__ out) {
    extern __shared__ uint32_t smem[];

    int tid  = threadIdx.x;
    int nb   = blockIdx.x;   // 0..15
    int mb   = blockIdx.y;   // 0..63
    int wid  = tid >> 5, lane = tid & 31;
    int wm   = wid >> 2;     // 0..1
    int wn   = wid & 3;      // 0..3
    int g    = lane >> 2, c = lane & 3;

    const __nv_bfloat16* Xg = g_Xh + (size_t)mb * BM * KDIM;
    const uint32_t*      Wg = g_Wp + (size_t)nb * (128 * 32 * 32 * 4);

    float acc[4][8][4];
    #pragma unroll
    for (int mt = 0; mt < 4; mt++)
        #pragma unroll
        for (int ns = 0; ns < 8; ns++)
            #pragma unroll
            for (int r = 0; r < 4; r++) acc[mt][ns][r] = 0.0f;

    // Prologue: stages 0..2 in flight
    #pragma unroll
    for (int s = 0; s < STAGES - 1; s++) {
        load_tile(smem + s * STAGE_U32, s, Xg, Wg, tid);
        asm volatile("cp.async.commit_group;\n");
    }

    const int NIT = KDIM / BK;   // 128
    for (int ki = 0; ki < NIT; ki++) {
        asm volatile("cp.async.wait_group %0;\n" :: "n"(STAGES - 2));  // tile ki ready
        __syncthreads();   // data visible to all; slot (ki-1)%4 fully consumed

        // Prefetch tile ki+3 into slot (ki+3)%4 == (ki-1)%4
        if (ki + STAGES - 1 < NIT)
            load_tile(smem + ((ki + STAGES - 1) & 3) * STAGE_U32, ki + STAGES - 1, Xg, Wg, tid);
        asm volatile("cp.async.commit_group;\n");   // always commit (keeps count)

        const uint32_t* A_ = smem + (ki & 3) * STAGE_U32;
        const uint32_t* B_ = A_ + AS_U32;

        // B fragments: one LDS.128 per n-slice covers both k16 halves
        uint4 bv[8];
        #pragma unroll
        for (int ns = 0; ns < 8; ns++)
            bv[ns] = *(const uint4*)(B_ + ((wn * 8 + ns) * 32 + lane) * 4);

        #pragma unroll
        for (int h = 0; h < 2; h++) {            // two k16 steps in BK=32
            uint32_t afr[4][4];
            #pragma unroll
            for (int mt = 0; mt < 4; mt++) {
                const uint32_t* ap = A_ + (wm * 64 + mt * 16 + g) * AS_STRIDE + h * 8 + c;
                afr[mt][0] = ap[0];
                afr[mt][1] = ap[8 * AS_STRIDE];
                afr[mt][2] = ap[4];
                afr[mt][3] = ap[8 * AS_STRIDE + 4];
            }
            #pragma unroll
            for (int mt = 0; mt < 4; mt++) {
                #pragma unroll
                for (int ns = 0; ns < 8; ns++) {
                    uint32_t b0 = h ? bv[ns].z : bv[ns].x;
                    uint32_t b1 = h ? bv[ns].w : bv[ns].y;
                    mma_bf16(acc[mt][ns], afr[mt], b0, b1);
                }
            }
        }
    }

    // Epilogue: add bias, write fp32
    int nbase = nb * 256 + wn * 64;
    int mbase = mb * BM + wm * 64;
    float2 bcol[8];
    #pragma unroll
    for (int ns = 0; ns < 8; ns++) {
        int col = nbase + ns * 8 + 2 * c;
        bcol[ns] = make_float2(bias[col], bias[col + 1]);
    }
    #pragma unroll
    for (int mt = 0; mt < 4; mt++) {
        int r0 = mbase + mt * 16 + g;
        #pragma unroll
        for (int ns = 0; ns < 8; ns++) {
            int col = nbase + ns * 8 + 2 * c;
            float2 v0 = make_float2(acc[mt][ns][0] + bcol[ns].x, acc[mt][ns][1] + bcol[ns].y);
            float2 v1 = make_float2(acc[mt][ns][2] + bcol[ns].x, acc[mt][ns][3] + bcol[ns].y);
            *(float2*)(out + (size_t)r0 * NDIM + col)       = v0;
            *(float2*)(out + (size_t)(r0 + 8) * NDIM + col) = v1;
        }
    }
}

// ---------------------------------------------------------------------------
extern "C" void kernel_launch(void* const* d_in, const int* in_sizes, int n_in,
                              void* d_out, int out_size) {
    const float *x = nullptr, *a = nullptr, *b = nullptr, *bias = nullptr;
    for (int idx = 0; idx < n_in; ++idx) {
        int s = in_sizes[idx];
        if (s == NTOK * KDIM && !x) x = (const float*)d_in[idx];
        else if (s == RANK * 64 * 64) { if (!a) a = (const float*)d_in[idx]; else if (!b) b = (const float*)d_in[idx]; }
        else if (s == NDIM && !bias) bias = (const float*)d_in[idx];
    }
    if (!x)    x    = (const float*)d_in[0];
    if (!a)    a    = (const float*)d_in[1];
    if (!b)    b    = (const float*)d_in[2];
    if (!bias) bias = (const float*)d_in[3];
    float* out = (float*)d_out;

    cvt_x_kernel<<<(NTOK * KDIM) / 8 / 256, 256>>>(x);
    build_w_kernel<<<KDIM / 2, 256>>>(a, b);

    cudaFuncSetAttribute(gemm_kernel, cudaFuncAttributeMaxDynamicSharedMemorySize, SMEM_BYTES);
    dim3 grid(NDIM / BN, NTOK / BM);   // (16, 64)
    gemm_kernel<<<grid, NTHREADS, SMEM_BYTES>>>(bias, out);
}

// round 14
// speedup vs baseline: 8.4108x; 1.0262x over previous
#include <cuda_runtime.h>
#include <cuda_bf16.h>
#include <cstdint>

// ---------------------------------------------------------------------------
// Problem constants
// ---------------------------------------------------------------------------
#define RANK   64
#define NTOK   8192
#define KDIM   4096   // A1*B1 (GEMM contraction dim)
#define NDIM   4096   // A2*B2 (GEMM output cols)

// GEMM tiling: BM=128, BN=128, BK=32, 256 threads (8 warps 2x4, 64x32 warp tile)
// 2 CTAs per SM (launch_bounds minBlocks=2, 73.7 KB smem/CTA)
#define BM 128
#define BN 128
#define BK 32
#define NTHREADS 256
#define STAGES 4
// A stage: 128 rows x 16 u32 (bf16 k-pairs) padded to 20 -> conflict-free frag loads
#define AS_STRIDE 20
#define AS_U32 (BM * AS_STRIDE)              // 2560
#define BS_U32 (BN * BK / 2)                 // 2048 (fragment-ordered, contiguous)
#define STAGE_U32 (AS_U32 + BS_U32)          // 4608
#define SMEM_BYTES (STAGES * STAGE_U32 * 4)  // 73728

// Scratch (static __device__ globals are the sanctioned no-alloc scratch)
__device__ __nv_bfloat16 g_Xh[(size_t)NTOK * KDIM];  // bf16 x (64 MB)
__device__ uint32_t g_Wp[(size_t)KDIM * NDIM / 2];   // W bf16x2, B-fragment order (32 MB)

__device__ __forceinline__ void cp_async16(uint32_t* smem_dst, const void* gmem_src) {
    uint32_t s = (uint32_t)__cvta_generic_to_shared(smem_dst);
    asm volatile("cp.async.cg.shared.global [%0], [%1], 16;\n" :: "r"(s), "l"(gmem_src));
}

// m16n8k16 bf16 mma, fp32 accumulate
__device__ __forceinline__ void mma_bf16(float* d, const uint32_t* a, uint32_t b0, uint32_t b1) {
    asm volatile(
        "mma.sync.aligned.m16n8k16.row.col.f32.bf16.bf16.f32 "
        "{%0,%1,%2,%3}, {%4,%5,%6,%7}, {%8,%9}, {%0,%1,%2,%3};\n"
        : "+f"(d[0]), "+f"(d[1]), "+f"(d[2]), "+f"(d[3])
        : "r"(a[0]), "r"(a[1]), "r"(a[2]), "r"(a[3]), "r"(b0), "r"(b1));
}

__device__ __forceinline__ uint32_t pack_bf16x2(float lo, float hi) {
    __nv_bfloat162 h = __floats2bfloat162_rn(lo, hi);   // x = lo (low 16 bits)
    return *(uint32_t*)&h;
}

// ---------------------------------------------------------------------------
// Kernel 1: convert x fp32 -> bf16 (rn). 8 floats per thread.
// ---------------------------------------------------------------------------
__global__ void cvt_x_kernel(const float* __restrict__ x) {
    int i = blockIdx.x * blockDim.x + threadIdx.x;   // 8-float chunk index
    float4 v0 = ((const float4*)x)[i * 2];
    float4 v1 = ((const float4*)x)[i * 2 + 1];
    uint4 o;
    o.x = pack_bf16x2(v0.x, v0.y);
    o.y = pack_bf16x2(v0.z, v0.w);
    o.z = pack_bf16x2(v1.x, v1.y);
    o.w = pack_bf16x2(v1.z, v1.w);
    ((uint4*)g_Xh)[i] = o;
}

// ---------------------------------------------------------------------------
// Kernel 2: build W[K][n] = sum_r a[r,i,j]*b[r,kk,l] (K = i*64+kk, n = j*64+l)
// in bf16, packed as (K even, K odd) pairs in m16n8k16 B-fragment order
// for BN=128 tiles:
//   g_Wp[nb][k32][nsG][lane][q] : nb = n>>7, nsG = (n>>3)&15, g = n&7,
//   lane = g*4 + c, q = 2*half + (koff>=8), K = k32*32 + half*16 + koff,
//   koff even, c = (koff&7)>>1, u32 = {lo: W[K][n], hi: W[K+1][n]}.
// One CTA per even K (2048 CTAs); fp32 accumulation. (Mapping verified R8.)
// ---------------------------------------------------------------------------
__global__ void __launch_bounds__(256) build_w_kernel(const float* __restrict__ a,
                                                      const float* __restrict__ b) {
    __shared__ float sA [64 * 64];   // a[r][j] for fixed i
    __shared__ float sB0[64 * 64];   // b[r][kk][l]
    __shared__ float sB1[64 * 64];   // b[r][kk+1][l]
    int K0 = blockIdx.x * 2;         // even K
    int i  = K0 >> 6, kk = K0 & 63;
    int tid = threadIdx.x;

    for (int idx = tid; idx < 4096; idx += 256) {
        int r = idx >> 6, col = idx & 63;
        sA [idx] = a[r * 4096 + i * 64 + col];
        sB0[idx] = b[r * 4096 + kk * 64 + col];
        sB1[idx] = b[r * 4096 + (kk + 1) * 64 + col];
    }
    __syncthreads();

    int tj = tid >> 4, tl = tid & 15;
    float accE[4][4], accO[4][4];
    #pragma unroll
    for (int jj = 0; jj < 4; jj++)
        #pragma unroll
        for (int ll = 0; ll < 4; ll++) { accE[jj][ll] = 0.0f; accO[jj][ll] = 0.0f; }

    const float4* A4  = (const float4*)sA;
    const float4* B04 = (const float4*)sB0;
    const float4* B14 = (const float4*)sB1;
    #pragma unroll 4
    for (int r = 0; r < 64; r++) {
        float4 av  = A4 [r * 16 + tj];
        float4 bv0 = B04[r * 16 + tl];
        float4 bv1 = B14[r * 16 + tl];
        float aj[4]  = {av.x, av.y, av.z, av.w};
        float bE[4]  = {bv0.x, bv0.y, bv0.z, bv0.w};
        float bO[4]  = {bv1.x, bv1.y, bv1.z, bv1.w};
        #pragma unroll
        for (int jj = 0; jj < 4; jj++)
            #pragma unroll
            for (int ll = 0; ll < 4; ll++) {
                accE[jj][ll] = fmaf(aj[jj], bE[ll], accE[jj][ll]);
                accO[jj][ll] = fmaf(aj[jj], bO[ll], accO[jj][ll]);
            }
    }

    int k32  = K0 >> 5;
    int r5   = K0 & 31;
    int half = r5 >> 4;
    int koff = r5 & 15;                 // even
    int c    = (koff & 7) >> 1;
    int q    = 2 * half + (koff >= 8 ? 1 : 0);

    #pragma unroll
    for (int jj = 0; jj < 4; jj++) {
        int j = tj * 4 + jj;
        #pragma unroll
        for (int ll = 0; ll < 4; ll++) {
            int l  = tl * 4 + ll;
            int n  = j * 64 + l;
            int nb = n >> 7, nsG = (n >> 3) & 15, g = n & 7;
            int lane = (g << 2) | c;
            size_t idx = ((((size_t)nb * 128 + k32) * 16 + nsG) * 32 + lane) * 4 + q;
            g_Wp[idx] = pack_bf16x2(accE[jj][ll], accO[jj][ll]);
        }
    }
}

// ---------------------------------------------------------------------------
// Kernel 3: GEMM out[8192,4096] = x @ W + bias, bf16 mma, fp32 accum.
// BM=128, BN=128, BK=32; 4-stage cp.async ring, wait_group 2, one sync/iter;
// 2 CTAs per SM so barrier/LDS stalls of one CTA hide under the other's MMAs.
// ---------------------------------------------------------------------------
__device__ __forceinline__ void load_tile(uint32_t* stage, int t,
                                          const __nv_bfloat16* Xg, const uint32_t* Wg,
                                          int tid) {
    // A: 128 rows x 32 bf16 (64B) -> 512 x 16B units (row = p>>2, u = p&3)
    uint32_t* As = stage;
    const __nv_bfloat16* xa = Xg + t * BK;
    #pragma unroll
    for (int it = 0; it < 2; it++) {
        int p = tid + it * NTHREADS;
        int row = p >> 2, u = p & 3;
        cp_async16(As + row * AS_STRIDE + u * 4, xa + (size_t)row * KDIM + u * 8);
    }
    // B: contiguous 8 KB fragment-ordered chunk (one k32 group) -> 512 x 16B units
    uint32_t* Bs = stage + AS_U32;
    const uint32_t* wb = Wg + (size_t)t * BS_U32;
    #pragma unroll
    for (int it = 0; it < 2; it++) {
        int p = tid + it * NTHREADS;
        cp_async16(Bs + p * 4, wb + p * 4);
    }
}

__global__ void __launch_bounds__(NTHREADS, 2)
gemm_kernel(const float* __restrict__ bias, float* __restrict__ out) {
    extern __shared__ uint32_t smem[];

    int tid  = threadIdx.x;
    int nb   = blockIdx.x;   // 0..31
    int mb   = blockIdx.y;   // 0..63
    int wid  = tid >> 5, lane = tid & 31;
    int wm   = wid >> 2;     // 0..1
    int wn   = wid & 3;      // 0..3
    int g    = lane >> 2, c = lane & 3;

    const __nv_bfloat16* Xg = g_Xh + (size_t)mb * BM * KDIM;
    const uint32_t*      Wg = g_Wp + (size_t)nb * ((size_t)128 * BS_U32);

    float acc[4][4][4];
    #pragma unroll
    for (int mt = 0; mt < 4; mt++)
        #pragma unroll
        for (int ns = 0; ns < 4; ns++)
            #pragma unroll
            for (int r = 0; r < 4; r++) acc[mt][ns][r] = 0.0f;

    // Prologue: stages 0..2 in flight
    #pragma unroll
    for (int s = 0; s < STAGES - 1; s++) {
        load_tile(smem + s * STAGE_U32, s, Xg, Wg, tid);
        asm volatile("cp.async.commit_group;\n");
    }

    const int NIT = KDIM / BK;   // 128
    for (int ki = 0; ki < NIT; ki++) {
        asm volatile("cp.async.wait_group %0;\n" :: "n"(STAGES - 2));  // tile ki ready
        __syncthreads();   // data visible to all; slot (ki-1)%4 fully consumed

        // Prefetch tile ki+3 into slot (ki+3)%4 == (ki-1)%4
        if (ki + STAGES - 1 < NIT)
            load_tile(smem + ((ki + STAGES - 1) & 3) * STAGE_U32, ki + STAGES - 1, Xg, Wg, tid);
        asm volatile("cp.async.commit_group;\n");   // always commit (keeps count)

        const uint32_t* A_ = smem + (ki & 3) * STAGE_U32;
        const uint32_t* B_ = A_ + AS_U32;

        // B fragments: one LDS.128 per n-slice covers both k16 halves
        uint4 bv[4];
        #pragma unroll
        for (int ns = 0; ns < 4; ns++)
            bv[ns] = *(const uint4*)(B_ + ((wn * 4 + ns) * 32 + lane) * 4);

        #pragma unroll
        for (int h = 0; h < 2; h++) {            // two k16 steps in BK=32
            uint32_t afr[4][4];
            #pragma unroll
            for (int mt = 0; mt < 4; mt++) {
                const uint32_t* ap = A_ + (wm * 64 + mt * 16 + g) * AS_STRIDE + h * 8 + c;
                afr[mt][0] = ap[0];
                afr[mt][1] = ap[8 * AS_STRIDE];
                afr[mt][2] = ap[4];
                afr[mt][3] = ap[8 * AS_STRIDE + 4];
            }
            #pragma unroll
            for (int mt = 0; mt < 4; mt++) {
                #pragma unroll
                for (int ns = 0; ns < 4; ns++) {
                    uint32_t b0 = h ? bv[ns].z : bv[ns].x;
                    uint32_t b1 = h ? bv[ns].w : bv[ns].y;
                    mma_bf16(acc[mt][ns], afr[mt], b0, b1);
                }
            }
        }
    }

    // Epilogue: add bias, write fp32
    int nbase = nb * BN + wn * 32;
    int mbase = mb * BM + wm * 64;
    float2 bcol[4];
    #pragma unroll
    for (int ns = 0; ns < 4; ns++) {
        int col = nbase + ns * 8 + 2 * c;
        bcol[ns] = make_float2(bias[col], bias[col + 1]);
    }
    #pragma unroll
    for (int mt = 0; mt < 4; mt++) {
        int r0 = mbase + mt * 16 + g;
        #pragma unroll
        for (int ns = 0; ns < 4; ns++) {
            int col = nbase + ns * 8 + 2 * c;
            float2 v0 = make_float2(acc[mt][ns][0] + bcol[ns].x, acc[mt][ns][1] + bcol[ns].y);
            float2 v1 = make_float2(acc[mt][ns][2] + bcol[ns].x, acc[mt][ns][3] + bcol[ns].y);
            *(float2*)(out + (size_t)r0 * NDIM + col)       = v0;
            *(float2*)(out + (size_t)(r0 + 8) * NDIM + col) = v1;
        }
    }
}

// ---------------------------------------------------------------------------
extern "C" void kernel_launch(void* const* d_in, const int* in_sizes, int n_in,
                              void* d_out, int out_size) {
    const float *x = nullptr, *a = nullptr, *b = nullptr, *bias = nullptr;
    for (int idx = 0; idx < n_in; ++idx) {
        int s = in_sizes[idx];
        if (s == NTOK * KDIM && !x) x = (const float*)d_in[idx];
        else if (s == RANK * 64 * 64) { if (!a) a = (const float*)d_in[idx]; else if (!b) b = (const float*)d_in[idx]; }
        else if (s == NDIM && !bias) bias = (const float*)d_in[idx];
    }
    if (!x)    x    = (const float*)d_in[0];
    if (!a)    a    = (const float*)d_in[1];
    if (!b)    b    = (const float*)d_in[2];
    if (!bias) bias = (const float*)d_in[3];
    float* out = (float*)d_out;

    cvt_x_kernel<<<(NTOK * KDIM) / 8 / 256, 256>>>(x);
    build_w_kernel<<<KDIM / 2, 256>>>(a, b);

    cudaFuncSetAttribute(gemm_kernel, cudaFuncAttributeMaxDynamicSharedMemorySize, SMEM_BYTES);
    dim3 grid(NDIM / BN, NTOK / BM);   // (32, 64)
    gemm_kernel<<<grid, NTHREADS, SMEM_BYTES>>>(bias, out);
}

// round 15
// speedup vs baseline: 9.7850x; 1.1634x over previous
#include <cuda_runtime.h>
#include <cuda_bf16.h>
#include <cstdint>

// ---------------------------------------------------------------------------
// Problem constants
// ---------------------------------------------------------------------------
#define RANK   64
#define NTOK   8192
#define KDIM   4096   // A1*B1 (GEMM contraction dim)
#define NDIM   4096   // A2*B2 (GEMM output cols)

// GEMM tiling: BM=128, BN=128, BK=64, 256 threads (8 warps 2x4, 64x32 warp tile)
// 2 CTAs per SM (launch_bounds minBlocks=2, ~102 KB smem/CTA)
#define BM 128
#define BN 128
#define BK 64
#define NTHREADS 256
#define STAGES 3
// A stage: 128 rows x 32 u32 (bf16 k-pairs) padded to 36 -> (4g+c)%32 conflict-free
#define AS_STRIDE 36
#define AS_U32 (BM * AS_STRIDE)              // 4608
#define BS_U32 (BN * BK / 2)                 // 4096 (two k32 fragment groups, contiguous)
#define STAGE_U32 (AS_U32 + BS_U32)          // 8704
#define SMEM_BYTES (STAGES * STAGE_U32 * 4)  // 104448

// Prologue fused-kernel block split
#define BW_BLOCKS 2048                        // build_w: one per even K
#define CVT_BLOCKS ((NTOK * KDIM) / 8 / 256)  // 16384

// Scratch (static __device__ globals are the sanctioned no-alloc scratch)
__device__ __nv_bfloat16 g_Xh[(size_t)NTOK * KDIM];  // bf16 x (64 MB)
__device__ uint32_t g_Wp[(size_t)KDIM * NDIM / 2];   // W bf16x2, B-fragment order (32 MB)

__device__ __forceinline__ void cp_async16(uint32_t* smem_dst, const void* gmem_src) {
    uint32_t s = (uint32_t)__cvta_generic_to_shared(smem_dst);
    asm volatile("cp.async.cg.shared.global [%0], [%1], 16;\n" :: "r"(s), "l"(gmem_src));
}

// m16n8k16 bf16 mma, fp32 accumulate
__device__ __forceinline__ void mma_bf16(float* d, const uint32_t* a, uint32_t b0, uint32_t b1) {
    asm volatile(
        "mma.sync.aligned.m16n8k16.row.col.f32.bf16.bf16.f32 "
        "{%0,%1,%2,%3}, {%4,%5,%6,%7}, {%8,%9}, {%0,%1,%2,%3};\n"
        : "+f"(d[0]), "+f"(d[1]), "+f"(d[2]), "+f"(d[3])
        : "r"(a[0]), "r"(a[1]), "r"(a[2]), "r"(a[3]), "r"(b0), "r"(b1));
}

__device__ __forceinline__ uint32_t pack_bf16x2(float lo, float hi) {
    __nv_bfloat162 h = __floats2bfloat162_rn(lo, hi);   // x = lo (low 16 bits)
    return *(uint32_t*)&h;
}

// ---------------------------------------------------------------------------
// Fused prologue kernel.
//  blocks [0, BW_BLOCKS):              build_w (FMA-bound, 48 KB smem)
//  blocks [BW_BLOCKS, BW_BLOCKS+CVT):  cvt x fp32 -> bf16 (DRAM-bound)
// The two phases overlap on different pipes instead of serializing.
//
// build_w: W[K][n] = sum_r a[r,i,j]*b[r,kk,l] (K = i*64+kk, n = j*64+l) in
// bf16, packed as (K even, K odd) pairs in m16n8k16 B-fragment order for
// BN=128 tiles:
//   g_Wp[nb][k32][nsG][lane][q] : nb = n>>7, nsG = (n>>3)&15, g = n&7,
//   lane = g*4 + c, q = 2*half + (koff>=8), K = k32*32 + half*16 + koff,
//   koff even, c = (koff&7)>>1, u32 = {lo: W[K][n], hi: W[K+1][n]}.
// (Mapping verified R8/R14.)
// ---------------------------------------------------------------------------
__global__ void __launch_bounds__(256) prologue_kernel(const float* __restrict__ x,
                                                       const float* __restrict__ a,
                                                       const float* __restrict__ b) {
    __shared__ float sbuf[3 * 4096];   // 48 KB
    int tid = threadIdx.x;

    if (blockIdx.x >= BW_BLOCKS) {
        // ---- cvt: 8 floats per thread ----
        int i = (blockIdx.x - BW_BLOCKS) * 256 + tid;
        float4 v0 = ((const float4*)x)[(size_t)i * 2];
        float4 v1 = ((const float4*)x)[(size_t)i * 2 + 1];
        uint4 o;
        o.x = pack_bf16x2(v0.x, v0.y);
        o.y = pack_bf16x2(v0.z, v0.w);
        o.z = pack_bf16x2(v1.x, v1.y);
        o.w = pack_bf16x2(v1.z, v1.w);
        ((uint4*)g_Xh)[i] = o;
        return;
    }

    // ---- build_w ----
    float* sA  = sbuf;            // a[r][j] for fixed i
    float* sB0 = sbuf + 4096;     // b[r][kk][l]
    float* sB1 = sbuf + 8192;     // b[r][kk+1][l]
    int K0 = blockIdx.x * 2;      // even K
    int i  = K0 >> 6, kk = K0 & 63;

    for (int idx = tid; idx < 4096; idx += 256) {
        int r = idx >> 6, col = idx & 63;
        sA [idx] = a[r * 4096 + i * 64 + col];
        sB0[idx] = b[r * 4096 + kk * 64 + col];
        sB1[idx] = b[r * 4096 + (kk + 1) * 64 + col];
    }
    __syncthreads();

    int tj = tid >> 4, tl = tid & 15;
    float accE[4][4], accO[4][4];
    #pragma unroll
    for (int jj = 0; jj < 4; jj++)
        #pragma unroll
        for (int ll = 0; ll < 4; ll++) { accE[jj][ll] = 0.0f; accO[jj][ll] = 0.0f; }

    const float4* A4  = (const float4*)sA;
    const float4* B04 = (const float4*)sB0;
    const float4* B14 = (const float4*)sB1;
    #pragma unroll 4
    for (int r = 0; r < 64; r++) {
        float4 av  = A4 [r * 16 + tj];
        float4 bv0 = B04[r * 16 + tl];
        float4 bv1 = B14[r * 16 + tl];
        float aj[4]  = {av.x, av.y, av.z, av.w};
        float bE[4]  = {bv0.x, bv0.y, bv0.z, bv0.w};
        float bO[4]  = {bv1.x, bv1.y, bv1.z, bv1.w};
        #pragma unroll
        for (int jj = 0; jj < 4; jj++)
            #pragma unroll
            for (int ll = 0; ll < 4; ll++) {
                accE[jj][ll] = fmaf(aj[jj], bE[ll], accE[jj][ll]);
                accO[jj][ll] = fmaf(aj[jj], bO[ll], accO[jj][ll]);
            }
    }

    int k32  = K0 >> 5;
    int r5   = K0 & 31;
    int half = r5 >> 4;
    int koff = r5 & 15;                 // even
    int c    = (koff & 7) >> 1;
    int q    = 2 * half + (koff >= 8 ? 1 : 0);

    #pragma unroll
    for (int jj = 0; jj < 4; jj++) {
        int j = tj * 4 + jj;
        #pragma unroll
        for (int ll = 0; ll < 4; ll++) {
            int l  = tl * 4 + ll;
            int n  = j * 64 + l;
            int nb = n >> 7, nsG = (n >> 3) & 15, g = n & 7;
            int lane = (g << 2) | c;
            size_t idx = ((((size_t)nb * 128 + k32) * 16 + nsG) * 32 + lane) * 4 + q;
            g_Wp[idx] = pack_bf16x2(accE[jj][ll], accO[jj][ll]);
        }
    }
}

// ---------------------------------------------------------------------------
// GEMM out[8192,4096] = x @ W + bias, bf16 mma, fp32 accum.
// BM=128, BN=128, BK=64; 3-stage cp.async ring, wait_group 1, one sync/iter;
// 2 CTAs per SM. 64 mainloop iterations (half the barrier count of BK=32).
// ---------------------------------------------------------------------------
__device__ __forceinline__ void load_tile(uint32_t* stage, int t,
                                          const __nv_bfloat16* Xg, const uint32_t* Wg,
                                          int tid) {
    // A: 128 rows x 64 bf16 (128B) -> 1024 x 16B units (row = p>>3, u = p&7)
    uint32_t* As = stage;
    const __nv_bfloat16* xa = Xg + t * BK;
    #pragma unroll
    for (int it = 0; it < 4; it++) {
        int p = tid + it * NTHREADS;
        int row = p >> 3, u = p & 7;
        cp_async16(As + row * AS_STRIDE + u * 4, xa + (size_t)row * KDIM + u * 8);
    }
    // B: contiguous 16 KB fragment-ordered chunk (two k32 groups) -> 1024 x 16B units
    uint32_t* Bs = stage + AS_U32;
    const uint32_t* wb = Wg + (size_t)t * BS_U32;
    #pragma unroll
    for (int it = 0; it < 4; it++) {
        int p = tid + it * NTHREADS;
        cp_async16(Bs + p * 4, wb + p * 4);
    }
}

__global__ void __launch_bounds__(NTHREADS, 2)
gemm_kernel(const float* __restrict__ bias, float* __restrict__ out) {
    extern __shared__ uint32_t smem[];

    int tid  = threadIdx.x;
    int nb   = blockIdx.x;   // 0..31
    int mb   = blockIdx.y;   // 0..63
    int wid  = tid >> 5, lane = tid & 31;
    int wm   = wid >> 2;     // 0..1
    int wn   = wid & 3;      // 0..3
    int g    = lane >> 2, c = lane & 3;

    const __nv_bfloat16* Xg = g_Xh + (size_t)mb * BM * KDIM;
    const uint32_t*      Wg = g_Wp + (size_t)nb * ((size_t)128 * 2048);  // per-nb W block

    float acc[4][4][4];
    #pragma unroll
    for (int mt = 0; mt < 4; mt++)
        #pragma unroll
        for (int ns = 0; ns < 4; ns++)
            #pragma unroll
            for (int r = 0; r < 4; r++) acc[mt][ns][r] = 0.0f;

    // Prologue: stages 0,1 in flight
    #pragma unroll
    for (int s = 0; s < STAGES - 1; s++) {
        load_tile(smem + s * STAGE_U32, s, Xg, Wg, tid);
        asm volatile("cp.async.commit_group;\n");
    }

    const int NIT = KDIM / BK;   // 64
    int s_cur = 0, s_nxt = STAGES - 1;
    for (int ki = 0; ki < NIT; ki++) {
        asm volatile("cp.async.wait_group %0;\n" :: "n"(STAGES - 2));  // tile ki ready
        __syncthreads();   // data visible to all; slot s_nxt fully consumed

        // Prefetch tile ki+2 into the slot freed last iteration
        if (ki + STAGES - 1 < NIT)
            load_tile(smem + s_nxt * STAGE_U32, ki + STAGES - 1, Xg, Wg, tid);
        asm volatile("cp.async.commit_group;\n");   // always commit (keeps count)

        const uint32_t* A_ = smem + s_cur * STAGE_U32;
        const uint32_t* B_ = A_ + AS_U32;

        #pragma unroll
        for (int sub = 0; sub < 2; sub++) {          // two k32 groups in BK=64
            // B fragments: one LDS.128 per n-slice covers both k16 halves of this k32
            uint4 bv[4];
            #pragma unroll
            for (int ns = 0; ns < 4; ns++)
                bv[ns] = *(const uint4*)(B_ + sub * 2048 + ((wn * 4 + ns) * 32 + lane) * 4);

            #pragma unroll
            for (int h = 0; h < 2; h++) {            // two k16 steps per k32
                uint32_t afr[4][4];
                #pragma unroll
                for (int mt = 0; mt < 4; mt++) {
                    const uint32_t* ap = A_ + (wm * 64 + mt * 16 + g) * AS_STRIDE
                                            + sub * 16 + h * 8 + c;
                    afr[mt][0] = ap[0];
                    afr[mt][1] = ap[8 * AS_STRIDE];
                    afr[mt][2] = ap[4];
                    afr[mt][3] = ap[8 * AS_STRIDE + 4];
                }
                #pragma unroll
                for (int mt = 0; mt < 4; mt++) {
                    #pragma unroll
                    for (int ns = 0; ns < 4; ns++) {
                        uint32_t b0 = h ? bv[ns].z : bv[ns].x;
                        uint32_t b1 = h ? bv[ns].w : bv[ns].y;
                        mma_bf16(acc[mt][ns], afr[mt], b0, b1);
                    }
                }
            }
        }

        s_nxt = s_cur;
        s_cur = (s_cur + 1 == STAGES) ? 0 : s_cur + 1;
    }

    // Epilogue: add bias, write fp32
    int nbase = nb * BN + wn * 32;
    int mbase = mb * BM + wm * 64;
    float2 bcol[4];
    #pragma unroll
    for (int ns = 0; ns < 4; ns++) {
        int col = nbase + ns * 8 + 2 * c;
        bcol[ns] = make_float2(bias[col], bias[col + 1]);
    }
    #pragma unroll
    for (int mt = 0; mt < 4; mt++) {
        int r0 = mbase + mt * 16 + g;
        #pragma unroll
        for (int ns = 0; ns < 4; ns++) {
            int col = nbase + ns * 8 + 2 * c;
            float2 v0 = make_float2(acc[mt][ns][0] + bcol[ns].x, acc[mt][ns][1] + bcol[ns].y);
            float2 v1 = make_float2(acc[mt][ns][2] + bcol[ns].x, acc[mt][ns][3] + bcol[ns].y);
            *(float2*)(out + (size_t)r0 * NDIM + col)       = v0;
            *(float2*)(out + (size_t)(r0 + 8) * NDIM + col) = v1;
        }
    }
}

// ---------------------------------------------------------------------------
extern "C" void kernel_launch(void* const* d_in, const int* in_sizes, int n_in,
                              void* d_out, int out_size) {
    const float *x = nullptr, *a = nullptr, *b = nullptr, *bias = nullptr;
    for (int idx = 0; idx < n_in; ++idx) {
        int s = in_sizes[idx];
        if (s == NTOK * KDIM && !x) x = (const float*)d_in[idx];
        else if (s == RANK * 64 * 64) { if (!a) a = (const float*)d_in[idx]; else if (!b) b = (const float*)d_in[idx]; }
        else if (s == NDIM && !bias) bias = (const float*)d_in[idx];
    }
    if (!x)    x    = (const float*)d_in[0];
    if (!a)    a    = (const float*)d_in[1];
    if (!b)    b    = (const float*)d_in[2];
    if (!bias) bias = (const float*)d_in[3];
    float* out = (float*)d_out;

    prologue_kernel<<<BW_BLOCKS + CVT_BLOCKS, 256>>>(x, a, b);

    cudaFuncSetAttribute(gemm_kernel, cudaFuncAttributeMaxDynamicSharedMemorySize, SMEM_BYTES);
    dim3 grid(NDIM / BN, NTOK / BM);   // (32, 64)
    gemm_kernel<<<grid, NTHREADS, SMEM_BYTES>>>(bias, out);
}